// round 12
// baseline (speedup 1.0000x reference)
#include <cuda_runtime.h>
#include <cuda_bf16.h>
#include <cstdint>

// BispectrumCalculator: target [B=32, T=4, N=512] f32
//   y = fft(target);  Bx[k,l] = y[k]*conj(y[l])*y[(l-k)%N]
//   source[b,{re,im},k,l] = mean_t Bx;  out = concat(source, target)
//
// Real-input symmetries (all exact identities):
//   H:   Bx[l,k]             = conj(Bx[k,l])
//   Neg: Bx[(N-k)%N,(N-l)%N] = conj(Bx[k,l])
//   HN:  Bx[(N-l)%N,(N-k)%N] =      Bx[k,l]
// Fundamental domain D = {k<=l && k+l<=N}. Emission guards give every output
// location exactly ONE producer (deterministic):
//   direct: D;  H: D && k<l;  Neg: D && k>=1 && k+l<N;  HN: D && k<l && k>=1 && k+l<N
// Tile set {ti<=tj, ti+tj<=7} covers D except points (64p, 512-64p), p=1..4,
// which are handled by 4 threads of the (b, y=0) block.

#define B_DIM 32
#define T_DIM 4
#define N_DIM 512
#define NROWS (B_DIM * T_DIM)                           // 128
#define SRC_ELEMS ((size_t)B_DIM * 2 * N_DIM * N_DIM)   // 16,777,216
#define TGT_ELEMS (B_DIM * T_DIM * N_DIM)               // 65,536
#define NN (N_DIM * N_DIM)                              // 262,144
#define NTILES 20
#define NYB (NTILES * 2)                                // 40 half-tile blocks
#define TP 33                                           // transpose pad stride

__constant__ int c_ti[NTILES] = {0,0,0,0,0,0,0,0, 1,1,1,1,1,1, 2,2,2,2, 3,3};
__constant__ int c_tj[NTILES] = {0,1,2,3,4,5,6,7, 1,2,3,4,5,6, 2,3,4,5, 3,4};

// FFT results, t-paired: g_y2[b][p][n] = float4(y_{2p}[n].re, y_{2p}[n].im,
//                                               y_{2p+1}[n].re, y_{2p+1}[n].im)
__device__ float4 g_y2[B_DIM * 2 * N_DIM];

// ---------------------------------------------------------------------------
// Kernel 1: 512-point radix-2 DIT FFT, one row per block, 256 threads.
//   Stages len<=32 are warp-local; final stage needs no sync before store.
//   Also copies the target tail into the output.
// ---------------------------------------------------------------------------
__global__ void fft512_kernel(const float* __restrict__ x,
                              float* __restrict__ out, int copy_tail) {
    __shared__ float2 s[N_DIM];
    const int row = blockIdx.x;          // 0..127
    const int tid = threadIdx.x;         // 0..255
    const float* xr = x + row * N_DIM;

    if (copy_tail && tid < 128) {        // 128 float4 = 512 floats per row
        ((float4*)(out + SRC_ELEMS + (size_t)row * N_DIM))[tid] =
            ((const float4*)xr)[tid];
    }

    #pragma unroll
    for (int i = tid; i < N_DIM; i += 256) {
        int r = __brev((unsigned)i) >> 23;   // 9-bit bit reversal
        s[r] = make_float2(xr[i], 0.0f);
    }
    __syncthreads();

    #pragma unroll
    for (int len = 2; len <= N_DIM; len <<= 1) {
        int half = len >> 1;
        int j    = tid & (half - 1);
        int grp  = tid / half;
        int base = grp * len;
        float ang = -6.283185307179586f * (float)j / (float)len;
        float wr, wi;
        __sincosf(ang, &wi, &wr);
        float2 a = s[base + j];
        float2 b = s[base + j + half];
        float tr = wr * b.x - wi * b.y;
        float ti = wr * b.y + wi * b.x;
        s[base + j]        = make_float2(a.x + tr, a.y + ti);
        s[base + j + half] = make_float2(a.x - tr, a.y - ti);
        if (len <= 32)        __syncwarp();      // stage stays in warp's 64-range
        else if (len < N_DIM) __syncthreads();   // len=64..256: next stage crosses
        // len == 512: final store below reads this thread's own writes
    }

    // Paired store: row = b*4 + t -> half (t&1) of float4 at [b*2 + t/2][i]
    const int b = row >> 2, t = row & 3;
    float2* dst = (float2*)g_y2 + ((size_t)((b * 2 + (t >> 1)) * N_DIM)) * 2 + (t & 1);
    #pragma unroll
    for (int i = tid; i < N_DIM; i += 256)
        dst[i * 2] = s[i];
}

// ---------------------------------------------------------------------------
// Kernel 2: bispectrum, 4-way symmetry.
//   grid = (32, 40); block = 512 threads.
//   yid -> tile (ti,tj) from tables, half = yid&1 -> k range of 32 rows.
//   Main pass: direct + Neg stores from registers; transpose buffer for H/HN.
//   Mirror pass: H + HN stores (coalesced) from the padded buffer.
// ---------------------------------------------------------------------------
__global__ __launch_bounds__(512, 3)
void bispec_kernel(float* __restrict__ out) {
    __shared__ float4 sy[2 * N_DIM];      // 16 KB
    __shared__ float stre[64 * TP];       // [lloc][kloc], pad 33
    __shared__ float stim[64 * TP];

    const int b   = blockIdx.x;
    const int yid = blockIdx.y;
    const int tid = threadIdx.x;
    const int tile_id = yid >> 1;
    const int K0 = c_ti[tile_id] * 64 + (yid & 1) * 32;
    const int L0 = c_tj[tile_id] * 64;
    const int tx  = tid & 63;             // l within tile
    const int tyg = tid >> 6;             // 0..7

    // Load y arrays (1024 float4 / 512 threads = 2 each)
    const float4* gy = g_y2 + b * (2 * N_DIM);
    sy[tid]       = gy[tid];
    sy[tid + 512] = gy[tid + 512];
    __syncthreads();

    const int l = L0 + tx;
    const float4 c01 = sy[l];             // conj side, t0/t1
    const float4 c23 = sy[N_DIM + l];     // conj side, t2/t3
    const int lneg = (N_DIM - l) & (N_DIM - 1);

    float* out_b = out + (size_t)b * (2u * NN);

    #pragma unroll
    for (int kk = 0; kk < 4; kk++) {
        const int kloc = tyg * 4 + kk;
        const int k = K0 + kloc;
        if (k <= l && k + l <= N_DIM) {   // fundamental domain
            const int m = (l - k) & (N_DIM - 1);

            float are, aim;
            {
                float4 A = sy[k];
                float4 D = sy[m];
                float pre = A.x * c01.x + A.y * c01.y;
                float pim = A.y * c01.x - A.x * c01.y;
                are = pre * D.x - pim * D.y;
                aim = pre * D.y + pim * D.x;
                pre = A.z * c01.z + A.w * c01.w;
                pim = A.w * c01.z - A.z * c01.w;
                are += pre * D.z - pim * D.w;
                aim += pre * D.w + pim * D.z;
            }
            {
                float4 A = sy[N_DIM + k];
                float4 D = sy[N_DIM + m];
                float pre = A.x * c23.x + A.y * c23.y;
                float pim = A.y * c23.x - A.x * c23.y;
                are += pre * D.x - pim * D.y;
                aim += pre * D.y + pim * D.x;
                pre = A.z * c23.z + A.w * c23.w;
                pim = A.w * c23.z - A.z * c23.w;
                are += pre * D.z - pim * D.w;
                aim += pre * D.w + pim * D.z;
            }
            are *= 0.25f;
            aim *= 0.25f;

            // direct: [k][l]
            const unsigned o = (unsigned)(k * N_DIM + l);
            out_b[o]      = are;
            out_b[o + NN] = aim;

            // Neg: [(N-k)][(N-l)] = conj  (k>=1 && k+l<N)
            if (k >= 1 && k + l < N_DIM) {
                const unsigned om = (unsigned)((N_DIM - k) * N_DIM + lneg);
                out_b[om]      = are;
                out_b[om + NN] = -aim;
            }

            // transpose buffer for H/HN mirror pass
            stre[tx * TP + kloc] = are;
            stim[tx * TP + kloc] = aim;
        }
    }

    // Special points (64p, 512-64p), p=1..4: not in any tile of the set.
    if (yid == 0 && tid < 4) {
        const int k = 64 * (tid + 1);
        const int lsp = N_DIM - k;
        const int m = (lsp - k) & (N_DIM - 1);
        const float4 s01 = sy[lsp], s23 = sy[N_DIM + lsp];
        float are, aim;
        {
            float4 A = sy[k];
            float4 D = sy[m];
            float pre = A.x * s01.x + A.y * s01.y;
            float pim = A.y * s01.x - A.x * s01.y;
            are = pre * D.x - pim * D.y;
            aim = pre * D.y + pim * D.x;
            pre = A.z * s01.z + A.w * s01.w;
            pim = A.w * s01.z - A.z * s01.w;
            are += pre * D.z - pim * D.w;
            aim += pre * D.w + pim * D.z;
        }
        {
            float4 A = sy[N_DIM + k];
            float4 D = sy[N_DIM + m];
            float pre = A.x * s23.x + A.y * s23.y;
            float pim = A.y * s23.x - A.x * s23.y;
            are += pre * D.x - pim * D.y;
            aim += pre * D.y + pim * D.x;
            pre = A.z * s23.z + A.w * s23.w;
            pim = A.w * s23.z - A.z * s23.w;
            are += pre * D.z - pim * D.w;
            aim += pre * D.w + pim * D.z;
        }
        are *= 0.25f;
        aim *= 0.25f;
        const unsigned o = (unsigned)(k * N_DIM + lsp);
        out_b[o]      = are;
        out_b[o + NN] = aim;
        if (k < lsp) {                    // H mirror (skip self-sym (256,256))
            const unsigned oh = (unsigned)(lsp * N_DIM + k);
            out_b[oh]      = are;
            out_b[oh + NN] = -aim;
        }
    }

    __syncthreads();

    // Mirror pass: H [l][k] = conj, HN [(N-l)][(N-k)] = same.
    const int c2 = tid & 31;
    #pragma unroll
    for (int i = 0; i < 4; i++) {
        const int r = (tid >> 5) + 16 * i;
        const int k = K0 + c2;
        const int lm = L0 + r;
        if (k < lm && k + lm <= N_DIM) {
            const float re = stre[r * TP + c2];
            const float im = stim[r * TP + c2];
            const unsigned oh = (unsigned)(lm * N_DIM + k);
            out_b[oh]      = re;
            out_b[oh + NN] = -im;
            if (k >= 1 && k + lm < N_DIM) {
                const unsigned on = (unsigned)((N_DIM - lm) * N_DIM + (N_DIM - k));
                out_b[on]      = re;
                out_b[on + NN] = im;
            }
        }
    }
}

extern "C" void kernel_launch(void* const* d_in, const int* in_sizes, int n_in,
                              void* d_out, int out_size) {
    const float* target = (const float*)d_in[0];
    float* out = (float*)d_out;

    const int copy_tail = ((size_t)out_size >= SRC_ELEMS + TGT_ELEMS) ? 1 : 0;

    fft512_kernel<<<NROWS, 256>>>(target, out, copy_tail);
    bispec_kernel<<<dim3(B_DIM, NYB), 512>>>(out);
}